// round 10
// baseline (speedup 1.0000x reference)
#include <cuda_runtime.h>

#define Bn 16
#define Cn 20
#define Hn 512
#define Wn 512
#define W4n (Wn / 4)
#define HWn (Hn * Wn)
#define HW4n (Hn * W4n)
#define CHWn (Cn * HWn)
#define HMASK (Hn - 1)
#define W4MASK (W4n - 1)

// Scratch (__device__ globals per allocation-free rule)
__device__ unsigned g_code[Bn * HW4n];  // per byte: a1[h] | a1[h+1]<<1 | a2[h]<<2 | a2[h+1]<<3

// exact 0/1-coefficient blend, BRANCHLESS: (1-a)(1-b)y + a*x + b*z
__device__ __forceinline__ float selv(bool a, bool b, float x, float y, float z) {
    float t = b ? z : y;
    t = a ? x : t;
    return (a && b) ? (x + z) : t;
}

// (df >= d) & (da < d) & (dfa < d)
__device__ __forceinline__ unsigned cmp3(float d, float df, float da, float dfa) {
    return (unsigned)(df >= d) & (unsigned)(da < d) & (unsigned)(dfa < d);
}

// ---------------- Kernel AB: fused mask pipeline -> packed control byte ----------------
// Row window indices i = 0..4 correspond to rows h-2+i.
// a1 at rows i=1..4, d1 at i=1..3 (vector + right lane), e1 at i=2..3, a2 at i=2..3.
__global__ void kAB(const float* __restrict__ world) {
    int idx = blockIdx.x * blockDim.x + threadIdx.x;   // b<<16 | h<<7 | w4
    int w4 = idx & W4MASK;
    int h  = (idx >> 7) & HMASK;
    int b  = idx >> 16;
    int w4m = (w4 - 1) & W4MASK, w4p = (w4 + 1) & W4MASK;

    const float4* c0 = (const float4*)(world + (long)b * CHWn);
    const float4* c1 = c0 + HW4n;
    const float* f0 = (const float*)c0;
    const float* f1 = (const float*)c1;

    int rofs[5];
#pragma unroll
    for (int i = 0; i < 5; i++) rofs[i] = ((h - 2 + i) & HMASK) * W4n;

    // loads: ch1 5 rows (vector + left .w + right .x), ch0 rows 1..4 (vector + right .x)
    float4 v1[5]; float l1[5], r1[5];
#pragma unroll
    for (int i = 0; i < 5; i++) {
        v1[i] = c1[rofs[i] + w4];
        l1[i] = f1[(rofs[i] + w4m) * 4 + 3];
        r1[i] = f1[(rofs[i] + w4p) * 4 + 0];
    }
    float4 v0[5]; float r0s[5];
#pragma unroll
    for (int i = 1; i < 5; i++) {
        v0[i] = c0[rofs[i] + w4];
        r0s[i] = f0[(rofs[i] + w4p) * 4 + 0];
    }

    // a1 for rows i=1..4 (4 vector lanes + right lane)
    unsigned a1x[5], a1y[5], a1z[5], a1w[5], a1r[5];
#pragma unroll
    for (int i = 1; i < 5; i++) {
        a1x[i] = (unsigned)(v0[i].x == 3.0f) & cmp3(v1[i].x, l1[i],    v1[i-1].x, l1[i-1]);
        a1y[i] = (unsigned)(v0[i].y == 3.0f) & cmp3(v1[i].y, v1[i].x,  v1[i-1].y, v1[i-1].x);
        a1z[i] = (unsigned)(v0[i].z == 3.0f) & cmp3(v1[i].z, v1[i].y,  v1[i-1].z, v1[i-1].y);
        a1w[i] = (unsigned)(v0[i].w == 3.0f) & cmp3(v1[i].w, v1[i].z,  v1[i-1].w, v1[i-1].z);
        a1r[i] = (unsigned)(r0s[i]  == 3.0f) & cmp3(r1[i],   v1[i].w,  r1[i-1],   v1[i-1].w);
    }

    // e1 for rows i=2,3 (vector lanes only) — consumes v0, then v0 dead
    unsigned e1x[4], e1y[4], e1z[4], e1w[4];
#pragma unroll
    for (int i = 2; i < 4; i++) {
        e1x[i] = (unsigned)(selv(a1x[i], a1x[i+1], v0[i-1].x, v0[i].x, v0[i+1].x) == 3.0f);
        e1y[i] = (unsigned)(selv(a1y[i], a1y[i+1], v0[i-1].y, v0[i].y, v0[i+1].y) == 3.0f);
        e1z[i] = (unsigned)(selv(a1z[i], a1z[i+1], v0[i-1].z, v0[i].z, v0[i+1].z) == 3.0f);
        e1w[i] = (unsigned)(selv(a1w[i], a1w[i+1], v0[i-1].w, v0[i].w, v0[i+1].w) == 3.0f);
    }

    // d1 for rows i=1..3 (vector + right lane) — consumes v1, then v1 dead
    float4 d1v[4]; float d1r[4];
#pragma unroll
    for (int i = 1; i < 4; i++) {
        d1v[i].x = selv(a1x[i], a1x[i+1], v1[i-1].x, v1[i].x, v1[i+1].x);
        d1v[i].y = selv(a1y[i], a1y[i+1], v1[i-1].y, v1[i].y, v1[i+1].y);
        d1v[i].z = selv(a1z[i], a1z[i+1], v1[i-1].z, v1[i].z, v1[i+1].z);
        d1v[i].w = selv(a1w[i], a1w[i+1], v1[i-1].w, v1[i].w, v1[i+1].w);
        d1r[i]   = selv(a1r[i], a1r[i+1], r1[i-1],   r1[i],   r1[i+1]);
    }

    // a2 for rows i=2,3
    unsigned a2x[4], a2y[4], a2z[4], a2w[4];
#pragma unroll
    for (int i = 2; i < 4; i++) {
        a2x[i] = e1x[i] & cmp3(d1v[i].x, d1v[i].y, d1v[i-1].x, d1v[i-1].y);
        a2y[i] = e1y[i] & cmp3(d1v[i].y, d1v[i].z, d1v[i-1].y, d1v[i-1].z);
        a2z[i] = e1z[i] & cmp3(d1v[i].z, d1v[i].w, d1v[i-1].z, d1v[i-1].w);
        a2w[i] = e1w[i] & cmp3(d1v[i].w, d1r[i],   d1v[i-1].w, d1r[i-1]);
    }

    unsigned code =
        (a1x[2] | (a1x[3] << 1) | (a2x[2] << 2) | (a2x[3] << 3))
      | ((a1y[2] | (a1y[3] << 1) | (a2y[2] << 2) | (a2y[3] << 3)) << 8)
      | ((a1z[2] | (a1z[3] << 1) | (a2z[2] << 2) | (a2z[3] << 3)) << 16)
      | ((a1w[2] | (a1w[3] << 1) | (a2w[2] << 2) | (a2w[3] << 3)) << 24);
    g_code[idx] = code;
}

// ---------------- Kernel C: fused two-step apply, 4-row batched loads ----------------
#define NCH 4
#define CHUNK (Hn / NCH)   // 128

__device__ __forceinline__ float4 w1vec(unsigned cw, float4 a, float4 b, float4 c) {
    float4 o;
    o.x = selv(cw & 0x00000001u, cw & 0x00000002u, a.x, b.x, c.x);
    o.y = selv(cw & 0x00000100u, cw & 0x00000200u, a.y, b.y, c.y);
    o.z = selv(cw & 0x00010000u, cw & 0x00020000u, a.z, b.z, c.z);
    o.w = selv(cw & 0x01000000u, cw & 0x02000000u, a.w, b.w, c.w);
    return o;
}
__device__ __forceinline__ float4 outvec(unsigned cw, float4 a, float4 b, float4 c) {
    float4 o;
    o.x = selv(cw & 0x00000004u, cw & 0x00000008u, a.x, b.x, c.x);
    o.y = selv(cw & 0x00000400u, cw & 0x00000800u, a.y, b.y, c.y);
    o.z = selv(cw & 0x00040000u, cw & 0x00080000u, a.z, b.z, c.z);
    o.w = selv(cw & 0x04000000u, cw & 0x08000000u, a.w, b.w, c.w);
    return o;
}

__global__ void __launch_bounds__(128, 8) kC(const float* __restrict__ world,
                                             float* __restrict__ out) {
    int w4 = threadIdx.x;                 // 0..127 — full row of float4
    int h0 = blockIdx.y * CHUNK;
    int bc = blockIdx.z;
    int b = bc / Cn;
    int c = bc - b * Cn;

    const float4* p = (const float4*)(world + (long)b * CHWn + (long)c * HWn);
    float4*       q = (float4*)(out + (long)b * CHWn + (long)c * HWn);
    const unsigned* ck = g_code + (b << 16);

    float4 r0 = __ldcs(p + ((h0 - 2) & HMASK) * W4n + w4);
    float4 r1 = __ldcs(p + ((h0 - 1) & HMASK) * W4n + w4);
    float4 r2 = __ldcs(p + h0 * W4n + w4);
    float4 r3 = __ldcs(p + ((h0 + 1) & HMASK) * W4n + w4);
    float4 r4 = __ldcs(p + ((h0 + 2) & HMASK) * W4n + w4);

    unsigned cm = ck[((h0 - 1) & HMASK) * W4n + w4];
    unsigned cc = ck[h0 * W4n + w4];
    unsigned cp = ck[((h0 + 1) & HMASK) * W4n + w4];

    float4 t0 = w1vec(cm, r0, r1, r2);   // w1[h0-1]
    float4 t1 = w1vec(cc, r1, r2, r3);   // w1[h0]
    float4 t2 = w1vec(cp, r2, r3, r4);   // w1[h0+1]

    for (int hh = 0; hh < CHUNK; hh += 4) {
        int h = h0 + hh;
        // ---- front-batched loads for the next 4 rows (MLP) ----
        float4 L0 = __ldcs(p + ((h + 3) & HMASK) * W4n + w4);
        float4 L1 = __ldcs(p + ((h + 4) & HMASK) * W4n + w4);
        float4 L2 = __ldcs(p + ((h + 5) & HMASK) * W4n + w4);
        float4 L3 = __ldcs(p + ((h + 6) & HMASK) * W4n + w4);
        unsigned C0 = ck[((h + 2) & HMASK) * W4n + w4];
        unsigned C1 = ck[((h + 3) & HMASK) * W4n + w4];
        unsigned C2 = ck[((h + 4) & HMASK) * W4n + w4];
        unsigned C3 = ck[((h + 5) & HMASK) * W4n + w4];

        // row h
        __stcs(q + h * W4n + w4, outvec(cc, t0, t1, t2));
        r0 = r1; r1 = r2; r2 = r3; r3 = r4; r4 = L0;
        t0 = t1; t1 = t2; t2 = w1vec(C0, r2, r3, r4);
        cc = cp; cp = C0;

        // row h+1
        __stcs(q + (h + 1) * W4n + w4, outvec(cc, t0, t1, t2));
        r0 = r1; r1 = r2; r2 = r3; r3 = r4; r4 = L1;
        t0 = t1; t1 = t2; t2 = w1vec(C1, r2, r3, r4);
        cc = cp; cp = C1;

        // row h+2
        __stcs(q + (h + 2) * W4n + w4, outvec(cc, t0, t1, t2));
        r0 = r1; r1 = r2; r2 = r3; r3 = r4; r4 = L2;
        t0 = t1; t1 = t2; t2 = w1vec(C2, r2, r3, r4);
        cc = cp; cp = C2;

        // row h+3
        __stcs(q + (h + 3) * W4n + w4, outvec(cc, t0, t1, t2));
        r0 = r1; r1 = r2; r2 = r3; r3 = r4; r4 = L3;
        t0 = t1; t1 = t2; t2 = w1vec(C3, r2, r3, r4);
        cc = cp; cp = C3;
    }
}

extern "C" void kernel_launch(void* const* d_in, const int* in_sizes, int n_in,
                              void* d_out, int out_size) {
    const float* world = (const float*)d_in[0];   // (16,20,512,512) fp32
    float* out = (float*)d_out;

    int nvec = Bn * HW4n;                 // 1,048,576
    kAB<<<nvec / 256, 256>>>(world);

    dim3 grid(1, NCH, Bn * Cn);           // (1, 4, 320)
    kC<<<grid, 128>>>(world, out);
}